// round 5
// baseline (speedup 1.0000x reference)
#include <cuda_runtime.h>
#include <cstdint>

// Problem shape (fixed by the dataset)
#define B  8
#define T  4096
#define D  1024
#define V4D (D / 4)                 // 256 float4 per full row

// Tiling: each CTA owns (batch, 128-float D-slice, 64 rows)
#define SLICES     8                // D / 128
#define SLICE_V4   32               // 128 floats = 32 float4
#define TILE_ROWS  64
#define GROUPS     8                // row groups per CTA (== warps)
#define RPG        8                // rows per group
#define CHUNK      4                // load batch (MLP)
#define THREADS    256
#define TILES      (T / TILE_ROWS)  // 64 tiles per chain
#define NCHAINS    (B * SLICES)     // 64 independent chains
#define NTILES     (NCHAINS * TILES)// 4096 CTAs

// dynamic smem layout (float4 units)
#define SM_C       0                                  // [TILE_ROWS][SLICE_V4]
#define SM_PART    (TILE_ROWS * SLICE_V4)             // [GROUPS][SLICE_V4]
#define SMEM_F4    (SM_PART + GROUPS * SLICE_V4)
#define SMEM_BYTES (SMEM_F4 * 16)                     // 36864 B -> 6 CTAs/SM

// Scratch (no allocations allowed — static __device__ globals)
__device__ float4 g_agg [NTILES * SLICE_V4];
__device__ int    g_flags[NTILES];
__device__ unsigned int g_ticket;

__device__ __forceinline__ void st_release(int* p, int v) {
    asm volatile("st.global.release.gpu.s32 [%0], %1;" :: "l"(p), "r"(v) : "memory");
}
__device__ __forceinline__ int ld_acquire(const int* p) {
    int v;
    asm volatile("ld.global.acquire.gpu.s32 %0, [%1];" : "=r"(v) : "l"(p) : "memory");
    return v;
}

// exact gelu via erff (polynomial, no MUFU exp path):
// jax.nn.gelu(approximate=False) = 0.5*x*(1+erf(x/sqrt(2)))
__device__ __forceinline__ float gelu_exact(float x) {
    return 0.5f * x * (1.0f + erff(x * 0.7071067811865475f));
}

// lengths dtype sniffing: reference asks for int64 but JAX default config
// (x64 disabled) emits int32. Reading the first 8 int32 words is safe under
// BOTH layouts. If genuine int64, every odd 32-bit word is the zero
// high-half (lengths < 4096). If int32, odd words are random lengths.
__device__ __forceinline__ int load_length(const void* lp, int b) {
    const int* p32 = (const int*)lp;
    bool is64 = (p32[1] == 0) & (p32[3] == 0) & (p32[5] == 0) & (p32[7] == 0);
    if (is64) return (int)((const long long*)lp)[b];
    return p32[b];
}

__global__ void init_kernel() {
    int i = blockIdx.x * blockDim.x + threadIdx.x;
    if (i < NTILES) g_flags[i] = 0;
    if (i == 0) g_ticket = 0u;
}

__global__ void __launch_bounds__(THREADS, 6)
scan_kernel(const float* __restrict__ x,
            const void* __restrict__ lengths,
            float* __restrict__ out) {
    extern __shared__ float4 smem[];
    __shared__ unsigned sh_v;

    const int tid = threadIdx.x;
    const int col = tid & 31;       // float4 column within slice
    const int grp = tid >> 5;       // row group (== warp id)

    // Ticket: tiles acquired in increasing order => all predecessors of any
    // running tile are resident or finished (no deadlock under graph replay).
    if (tid == 0) sh_v = atomicAdd(&g_ticket, 1u);
    __syncthreads();
    const unsigned v = sh_v;
    const int chain = v / TILES;    // (b, slice)
    const int p     = v % TILES;
    const int chain_base = chain * TILES;
    const int b     = chain / SLICES;
    const int s     = chain % SLICES;
    const int t0    = p * TILE_ROWS;
    const int len   = load_length(lengths, b);

    // gmem base for this thread: row (t0 + grp*RPG), slice s, column col
    const size_t row0 = (size_t)b * T + t0 + grp * RPG;
    const float4* x4 = reinterpret_cast<const float4*>(x)
                       + row0 * V4D + s * SLICE_V4 + col;

    // ---- Pass 1: load x once, gelu once, register-serial group prefix ----
    float4 run = make_float4(0.f, 0.f, 0.f, 0.f);
    #pragma unroll
    for (int i0 = 0; i0 < RPG; i0 += CHUNK) {
        float4 xv[CHUNK];
        #pragma unroll
        for (int k = 0; k < CHUNK; k++)            // batched loads: MLP >= 4
            xv[k] = x4[(size_t)(i0 + k) * V4D];
        #pragma unroll
        for (int k = 0; k < CHUNK; k++) {
            const int row = t0 + grp * RPG + i0 + k;
            float4 c;
            if (row < len) {                        // warp-uniform branch
                run.x += gelu_exact(xv[k].x);
                run.y += gelu_exact(xv[k].y);
                run.z += gelu_exact(xv[k].z);
                run.w += gelu_exact(xv[k].w);
                c.x = xv[k].x + run.x; c.y = xv[k].y + run.y;
                c.z = xv[k].z + run.z; c.w = xv[k].w + run.w;
            } else {
                c = xv[k];                          // masked row: out = x
            }
            smem[SM_C + (grp * RPG + i0 + k) * SLICE_V4 + col] = c;
        }
    }
    smem[SM_PART + grp * SLICE_V4 + col] = run;
    __syncthreads();

    // ---- group-exclusive offsets (<=7 LDS.128 per thread) ----
    float4 gex = make_float4(0.f, 0.f, 0.f, 0.f);
    for (int g = 0; g < grp; g++) {
        float4 a = smem[SM_PART + g * SLICE_V4 + col];
        gex.x += a.x; gex.y += a.y; gex.z += a.z; gex.w += a.w;
    }

    // ---- warp 7 publishes tile aggregate (release) ----
    if (grp == GROUPS - 1) {
        float4 agg;
        agg.x = gex.x + run.x; agg.y = gex.y + run.y;
        agg.z = gex.z + run.z; agg.w = gex.w + run.w;
        g_agg[(size_t)v * SLICE_V4 + col] = agg;
        __syncwarp();
        if (col == 0) { __threadfence(); st_release(&g_flags[v], 1); }
    }

    // ---- parallel gather of ALL predecessor aggregates ----
    float4 excl = make_float4(0.f, 0.f, 0.f, 0.f);
    if (p > 0) {                                    // block-uniform branch
        // warp 0: poll all p predecessor flags concurrently (acquire)
        if (grp == 0) {
            for (int j = col; j < p; j += 32) {
                const int* fp = &g_flags[chain_base + j];
                int f = ld_acquire(fp);
                while (f == 0) { __nanosleep(20); f = ld_acquire(fp); }
            }
        }
        __syncthreads();   // flags observed; SM_PART (gex) reads complete

        // all 8 warps gather: warp w takes predecessors w, w+8, w+16, ...
        float4 part = make_float4(0.f, 0.f, 0.f, 0.f);
        for (int j = grp; j < p; j += GROUPS) {
            float4 a = g_agg[(size_t)(chain_base + j) * SLICE_V4 + col];
            part.x += a.x; part.y += a.y; part.z += a.z; part.w += a.w;
        }
        smem[SM_PART + grp * SLICE_V4 + col] = part;   // reuse SM_PART
        __syncthreads();
        #pragma unroll
        for (int w = 0; w < GROUPS; w++) {
            float4 a = smem[SM_PART + w * SLICE_V4 + col];
            excl.x += a.x; excl.y += a.y; excl.z += a.z; excl.w += a.w;
        }
    }

    // ---- Pass 2: out = c + valid * (chain_excl + group_excl) ----
    float4 off;
    off.x = excl.x + gex.x; off.y = excl.y + gex.y;
    off.z = excl.z + gex.z; off.w = excl.w + gex.w;

    float4* o4 = reinterpret_cast<float4*>(out)
                 + row0 * V4D + s * SLICE_V4 + col;
    #pragma unroll
    for (int i = 0; i < RPG; i++) {
        const int row = t0 + grp * RPG + i;
        float4 c = smem[SM_C + (grp * RPG + i) * SLICE_V4 + col];
        float4 o;
        if (row < len) {                            // warp-uniform
            o.x = c.x + off.x; o.y = c.y + off.y;
            o.z = c.z + off.z; o.w = c.w + off.w;
        } else {
            o = c;
        }
        o4[(size_t)i * V4D] = o;
    }
}

extern "C" void kernel_launch(void* const* d_in, const int* in_sizes, int n_in,
                              void* d_out, int out_size) {
    const float* x   = (const float*)d_in[0];
    const void*  len = (const void*)d_in[1];
    float*       out = (float*)d_out;

    cudaFuncSetAttribute(scan_kernel,
                         cudaFuncAttributeMaxDynamicSharedMemorySize, SMEM_BYTES);

    init_kernel<<<(NTILES + 255) / 256, 256>>>();
    scan_kernel<<<NTILES, THREADS, SMEM_BYTES>>>(x, len, out);
}

// round 6
// speedup vs baseline: 1.1116x; 1.1116x over previous
#include <cuda_runtime.h>
#include <cstdint>

// Problem shape (fixed by the dataset)
#define B  8
#define T  4096
#define D  1024
#define V4D 256                     // float4 per row
#define SLICES 32                   // 32-float D-slices
#define SLICE_V4 8                  // 8 float4 per slice
#define TILE 128                    // rows per tile iteration
#define RPT  4                      // rows per thread per tile
#define THREADS 256                 // 32 q-blocks x 8 columns
#define ITERS (T / TILE)            // 32
#define NCTAS (B * SLICES)          // 256

// exact gelu via erff (polynomial path, no MUFU exp):
// jax.nn.gelu(approximate=False) = 0.5*x*(1+erf(x/sqrt(2)))
__device__ __forceinline__ float gelu_exact(float x) {
    return 0.5f * x * (1.0f + erff(x * 0.7071067811865476f));
}

// lengths dtype sniffing: reference asks for int64 but JAX default config
// (x64 disabled) emits int32. Reading the first 8 int32 words is safe under
// BOTH layouts. If genuine int64, every odd 32-bit word is the zero
// high-half (lengths < 4096). If int32, odd words are random lengths.
__device__ __forceinline__ int load_length(const void* lp, int b) {
    const int* p32 = (const int*)lp;
    bool is64 = (p32[1] == 0) & (p32[3] == 0) & (p32[5] == 0) & (p32[7] == 0);
    if (is64) return (int)((const long long*)lp)[b];
    return p32[b];
}

__global__ void __launch_bounds__(THREADS)
fused_kernel(const float* __restrict__ x,
             const void* __restrict__ lengths,
             float* __restrict__ out) {
    // c stash: [row][col], 128B rows -> 8-lane LDS/STS phases conflict-free
    __shared__ float4 c_sm[TILE][SLICE_V4];
    // partials padded to stride 9 so column-strided scan reads are conflict-free
    __shared__ float4 part[32 * 9];
    __shared__ float4 tot[SLICE_V4];

    const int tid  = threadIdx.x;
    const int q    = tid >> 3;      // row-block index  [0,32)
    const int l    = tid & 7;       // float4 column    [0,8)
    const int lane = tid & 31;
    const int w    = tid >> 5;      // warp id == scan column

    const int s = blockIdx.x & (SLICES - 1);
    const int b = blockIdx.x >> 5;
    const int len = load_length(lengths, b);

    const size_t colbase = (size_t)b * T * V4D + (size_t)s * SLICE_V4 + l;
    const float4* xp = reinterpret_cast<const float4*>(x);
    float4*       op = reinterpret_cast<float4*>(out);

    float4 carry = make_float4(0.f, 0.f, 0.f, 0.f);

    for (int it = 0; it < ITERS; it++) {
        const int t0 = it * TILE;
        const int r0 = t0 + q * RPT;

        if (t0 >= len) {
            // fully masked tile: out = x (CTA-uniform fast path, no smem/sync)
            float4 v[RPT];
            #pragma unroll
            for (int i = 0; i < RPT; i++)
                v[i] = __ldcs(xp + colbase + (size_t)(r0 + i) * V4D);
            #pragma unroll
            for (int i = 0; i < RPT; i++)
                __stcs(op + colbase + (size_t)(r0 + i) * V4D, v[i]);
            continue;
        }

        // ---- Pass 1: load (MLP=4), gelu once, per-thread serial prefix ----
        float4 xv[RPT];
        #pragma unroll
        for (int i = 0; i < RPT; i++)
            xv[i] = __ldcs(xp + colbase + (size_t)(r0 + i) * V4D);

        float4 run = make_float4(0.f, 0.f, 0.f, 0.f);
        #pragma unroll
        for (int i = 0; i < RPT; i++) {
            float4 c = xv[i];
            if (r0 + i < len) {
                run.x += gelu_exact(xv[i].x);
                run.y += gelu_exact(xv[i].y);
                run.z += gelu_exact(xv[i].z);
                run.w += gelu_exact(xv[i].w);
                c.x += run.x; c.y += run.y; c.z += run.z; c.w += run.w;
            }
            c_sm[q * RPT + i][l] = c;
        }
        part[q * 9 + l] = run;
        __syncthreads();

        // ---- warp w shuffle-scans the 32 partials of column w ----
        {
            float4 v = part[lane * 9 + w];
            float4 inc = v;
            #pragma unroll
            for (int d = 1; d < 32; d <<= 1) {
                float nx = __shfl_up_sync(0xffffffffu, inc.x, d);
                float ny = __shfl_up_sync(0xffffffffu, inc.y, d);
                float nz = __shfl_up_sync(0xffffffffu, inc.z, d);
                float nw = __shfl_up_sync(0xffffffffu, inc.w, d);
                if (lane >= d) { inc.x += nx; inc.y += ny; inc.z += nz; inc.w += nw; }
            }
            float4 ex;
            ex.x = inc.x - v.x; ex.y = inc.y - v.y;
            ex.z = inc.z - v.z; ex.w = inc.w - v.w;
            part[lane * 9 + w] = ex;            // exclusive, in place
            if (lane == 31) tot[w] = inc;       // tile total for column w
        }
        __syncthreads();

        // ---- Pass 2: out = c + valid * (carry + excl); advance carry ----
        float4 ex = part[q * 9 + l];
        float4 off;
        off.x = carry.x + ex.x; off.y = carry.y + ex.y;
        off.z = carry.z + ex.z; off.w = carry.w + ex.w;
        float4 tt = tot[l];
        carry.x += tt.x; carry.y += tt.y; carry.z += tt.z; carry.w += tt.w;

        #pragma unroll
        for (int i = 0; i < RPT; i++) {
            float4 c = c_sm[q * RPT + i][l];
            float4 o = c;
            if (r0 + i < len) {
                o.x = c.x + off.x; o.y = c.y + off.y;
                o.z = c.z + off.z; o.w = c.w + off.w;
            }
            __stcs(op + colbase + (size_t)(r0 + i) * V4D, o);
        }
        __syncthreads();   // protect c_sm/part/tot before next tile
    }
}

extern "C" void kernel_launch(void* const* d_in, const int* in_sizes, int n_in,
                              void* d_out, int out_size) {
    const float* x   = (const float*)d_in[0];
    const void*  len = (const void*)d_in[1];
    float*       out = (float*)d_out;

    fused_kernel<<<NCTAS, THREADS>>>(x, len, out);
}

// round 7
// speedup vs baseline: 1.2987x; 1.1683x over previous
#include <cuda_runtime.h>
#include <cstdint>

// Problem shape (fixed by the dataset)
#define B  8
#define T  4096
#define D  1024
#define V4D 256                     // float4 per row
#define SLICES 32                   // 32-float D-slices
#define SLICE_V4 8                  // 8 float4 per slice
#define TILE 128                    // rows per tile iteration
#define RPT  4                      // rows per thread per tile
#define THREADS 256                 // 32 q-blocks x 8 columns
#define ITERS (T / TILE)            // 32
#define NCTAS (B * SLICES)          // 256

// exact gelu via erff (polynomial path, no MUFU exp):
// jax.nn.gelu(approximate=False) = 0.5*x*(1+erf(x/sqrt(2)))
__device__ __forceinline__ float gelu_exact(float x) {
    return 0.5f * x * (1.0f + erff(x * 0.7071067811865476f));
}

// lengths dtype sniffing: reference asks for int64 but JAX default config
// (x64 disabled) emits int32. Reading the first 8 int32 words is safe under
// BOTH layouts. If genuine int64, every odd 32-bit word is the zero
// high-half (lengths < 4096). If int32, odd words are random lengths.
__device__ __forceinline__ int load_length(const void* lp, int b) {
    const int* p32 = (const int*)lp;
    bool is64 = (p32[1] == 0) & (p32[3] == 0) & (p32[5] == 0) & (p32[7] == 0);
    if (is64) return (int)((const long long*)lp)[b];
    return p32[b];
}

__global__ void __launch_bounds__(THREADS)
fused_kernel(const float* __restrict__ x,
             const void* __restrict__ lengths,
             float* __restrict__ out) {
    // double-buffered smem: removes the trailing barrier of each tile
    __shared__ float4 c_sm[2][TILE][SLICE_V4];   // 32 KB
    __shared__ float4 part[2][32 * 9];           // ~9 KB (stride 9: no conflicts)
    __shared__ float4 tot[2][SLICE_V4];

    const int tid  = threadIdx.x;
    const int q    = tid >> 3;      // row-block index  [0,32)
    const int l    = tid & 7;       // float4 column    [0,8)
    const int lane = tid & 31;
    const int w    = tid >> 5;      // warp id == scan column

    const int s = blockIdx.x & (SLICES - 1);
    const int b = blockIdx.x >> 5;
    const int len = load_length(lengths, b);
    const int nact = min(ITERS, (len + TILE - 1) / TILE);  // active tiles

    const size_t colbase = (size_t)b * T * V4D + (size_t)s * SLICE_V4 + l;
    const float4* xp = reinterpret_cast<const float4*>(x);
    float4*       op = reinterpret_cast<float4*>(out);

    float4 carry = make_float4(0.f, 0.f, 0.f, 0.f);

    // ================= Phase A: pipelined active tiles =================
    float4 cur[RPT];
    if (nact > 0) {
        const size_t base0 = colbase + (size_t)(q * RPT) * V4D;
        #pragma unroll
        for (int i = 0; i < RPT; i++)
            cur[i] = __ldcs(xp + base0 + (size_t)i * V4D);
    }

    for (int it = 0; it < nact; it++) {
        const int pb = it & 1;
        const int r0 = it * TILE + q * RPT;

        // ---- Pass 1: consume prefetched regs: gelu once, serial prefix ----
        float4 run = make_float4(0.f, 0.f, 0.f, 0.f);
        #pragma unroll
        for (int i = 0; i < RPT; i++) {
            float4 c = cur[i];
            if (r0 + i < len) {                 // warp-uniform
                run.x += gelu_exact(cur[i].x);
                run.y += gelu_exact(cur[i].y);
                run.z += gelu_exact(cur[i].z);
                run.w += gelu_exact(cur[i].w);
                c.x += run.x; c.y += run.y; c.z += run.z; c.w += run.w;
            }
            c_sm[pb][q * RPT + i][l] = c;
        }

        // ---- prefetch next tile NOW: loads fly during scan + pass 2 ----
        if (it + 1 < nact) {
            const size_t basen = colbase + (size_t)((it + 1) * TILE + q * RPT) * V4D;
            #pragma unroll
            for (int i = 0; i < RPT; i++)
                cur[i] = __ldcs(xp + basen + (size_t)i * V4D);
        }

        part[pb][q * 9 + l] = run;
        __syncthreads();

        // ---- warp w shuffle-scans the 32 partials of column w ----
        {
            float4 v = part[pb][lane * 9 + w];
            float4 inc = v;
            #pragma unroll
            for (int d = 1; d < 32; d <<= 1) {
                float nx = __shfl_up_sync(0xffffffffu, inc.x, d);
                float ny = __shfl_up_sync(0xffffffffu, inc.y, d);
                float nz = __shfl_up_sync(0xffffffffu, inc.z, d);
                float nw = __shfl_up_sync(0xffffffffu, inc.w, d);
                if (lane >= d) { inc.x += nx; inc.y += ny; inc.z += nz; inc.w += nw; }
            }
            float4 ex;
            ex.x = inc.x - v.x; ex.y = inc.y - v.y;
            ex.z = inc.z - v.z; ex.w = inc.w - v.w;
            part[pb][lane * 9 + w] = ex;        // exclusive, in place
            if (lane == 31) tot[pb][w] = inc;   // tile total for column w
        }
        __syncthreads();

        // ---- Pass 2: out = c + valid*(carry + excl); advance carry ----
        float4 ex = part[pb][q * 9 + l];
        float4 off;
        off.x = carry.x + ex.x; off.y = carry.y + ex.y;
        off.z = carry.z + ex.z; off.w = carry.w + ex.w;
        float4 tt = tot[pb][l];
        carry.x += tt.x; carry.y += tt.y; carry.z += tt.z; carry.w += tt.w;

        #pragma unroll
        for (int i = 0; i < RPT; i++) {
            float4 c = c_sm[pb][q * RPT + i][l];
            float4 o = c;
            if (r0 + i < len) {                 // warp-uniform
                o.x = c.x + off.x; o.y = c.y + off.y;
                o.z = c.z + off.z; o.w = c.w + off.w;
            }
            __stcs(op + colbase + (size_t)(r0 + i) * V4D, o);
        }
        // no trailing barrier: next tile uses the other smem buffer
    }

    // ============ Phase B: masked tail = pure streaming copy ============
    for (int it = nact; it < ITERS; it++) {
        const size_t base = colbase + (size_t)(it * TILE + q * RPT) * V4D;
        float4 v[RPT];
        #pragma unroll
        for (int i = 0; i < RPT; i++)
            v[i] = __ldcs(xp + base + (size_t)i * V4D);
        #pragma unroll
        for (int i = 0; i < RPT; i++)
            __stcs(op + base + (size_t)i * V4D, v[i]);
    }
}

extern "C" void kernel_launch(void* const* d_in, const int* in_sizes, int n_in,
                              void* d_out, int out_size) {
    const float* x   = (const float*)d_in[0];
    const void*  len = (const void*)d_in[1];
    float*       out = (float*)d_out;

    fused_kernel<<<NCTAS, THREADS>>>(x, len, out);
}

// round 8
// speedup vs baseline: 1.3059x; 1.0055x over previous
#include <cuda_runtime.h>
#include <cstdint>

// Problem shape (fixed by the dataset)
#define B  8
#define T  4096
#define D  1024
#define V4D 256                     // float4 per row
#define SLICES 64                   // 16-float D-slices
#define SLICE_V4 4                  // 4 float4 per slice
#define TILE 256                    // rows per tile iteration
#define QN   64                     // row-blocks per tile (TILE/RPT)
#define RPT  4                      // rows per thread per tile
#define THREADS 256                 // 64 q-blocks x 4 columns
#define ITERS (T / TILE)            // 16
#define NCTAS (B * SLICES)          // 512

// exact gelu via erff (polynomial path, no MUFU exp):
// jax.nn.gelu(approximate=False) = 0.5*x*(1+erf(x/sqrt(2)))
__device__ __forceinline__ float gelu_exact(float x) {
    return 0.5f * x * (1.0f + erff(x * 0.7071067811865476f));
}

// lengths dtype sniffing: reference asks for int64 but JAX default config
// (x64 disabled) emits int32. Reading the first 8 int32 words is safe under
// BOTH layouts. If genuine int64, every odd 32-bit word is the zero
// high-half (lengths < 4096). If int32, odd words are random lengths.
__device__ __forceinline__ int load_length(const void* lp, int b) {
    const int* p32 = (const int*)lp;
    bool is64 = (p32[1] == 0) & (p32[3] == 0) & (p32[5] == 0) & (p32[7] == 0);
    if (is64) return (int)((const long long*)lp)[b];
    return p32[b];
}

__global__ void __launch_bounds__(THREADS)
fused_kernel(const float* __restrict__ x,
             const void* __restrict__ lengths,
             float* __restrict__ out) {
    // double-buffered smem: no trailing barrier per tile
    __shared__ float4 c_sm[2][TILE][SLICE_V4];    // 32 KB
    __shared__ float4 part[2][QN * 5];            // stride 5: conflict-free
    __shared__ float4 htot[2][2][SLICE_V4];       // half-column totals

    const int tid  = threadIdx.x;
    const int q    = tid >> 2;      // row-block index  [0,64)
    const int l    = tid & 3;       // float4 column    [0,4)
    const int lane = tid & 31;
    const int w    = tid >> 5;      // warp id [0,8)
    const int cw   = w & 3;         // scan column of this warp
    const int hh   = w >> 2;        // scan half of this warp

    const int s = blockIdx.x & (SLICES - 1);
    const int b = blockIdx.x >> 6;
    const int len = load_length(lengths, b);
    const int nact = min(ITERS, (len + TILE - 1) / TILE);  // active tiles

    const size_t colbase = (size_t)b * T * V4D + (size_t)s * SLICE_V4 + l;
    const float4* xp = reinterpret_cast<const float4*>(x);
    float4*       op = reinterpret_cast<float4*>(out);

    float4 carry = make_float4(0.f, 0.f, 0.f, 0.f);

    // ================= Phase A: pipelined active tiles =================
    float4 cur[RPT];
    if (nact > 0) {
        const size_t base0 = colbase + (size_t)(q * RPT) * V4D;
        #pragma unroll
        for (int i = 0; i < RPT; i++)
            cur[i] = __ldcs(xp + base0 + (size_t)i * V4D);
    }

    for (int it = 0; it < nact; it++) {
        const int pb = it & 1;
        const int r0 = it * TILE + q * RPT;

        // ---- Pass 1: consume prefetched regs: gelu once, serial prefix ----
        float4 run = make_float4(0.f, 0.f, 0.f, 0.f);
        #pragma unroll
        for (int i = 0; i < RPT; i++) {
            float4 c = cur[i];
            if (r0 + i < len) {                 // warp-uniform
                run.x += gelu_exact(cur[i].x);
                run.y += gelu_exact(cur[i].y);
                run.z += gelu_exact(cur[i].z);
                run.w += gelu_exact(cur[i].w);
                c.x += run.x; c.y += run.y; c.z += run.z; c.w += run.w;
            }
            c_sm[pb][q * RPT + i][l] = c;
        }

        // ---- prefetch next tile NOW: loads fly during scan + pass 2 ----
        if (it + 1 < nact) {
            const size_t basen = colbase + (size_t)((it + 1) * TILE + q * RPT) * V4D;
            #pragma unroll
            for (int i = 0; i < RPT; i++)
                cur[i] = __ldcs(xp + basen + (size_t)i * V4D);
        }

        part[pb][q * 5 + l] = run;
        __syncthreads();

        // ---- two-level scan: warp w scans half hh of column cw ----
        {
            const int idx = hh * 32 + lane;
            float4 v = part[pb][idx * 5 + cw];
            float4 inc = v;
            #pragma unroll
            for (int d = 1; d < 32; d <<= 1) {
                float nx = __shfl_up_sync(0xffffffffu, inc.x, d);
                float ny = __shfl_up_sync(0xffffffffu, inc.y, d);
                float nz = __shfl_up_sync(0xffffffffu, inc.z, d);
                float nw = __shfl_up_sync(0xffffffffu, inc.w, d);
                if (lane >= d) { inc.x += nx; inc.y += ny; inc.z += nz; inc.w += nw; }
            }
            float4 ex;
            ex.x = inc.x - v.x; ex.y = inc.y - v.y;
            ex.z = inc.z - v.z; ex.w = inc.w - v.w;
            part[pb][idx * 5 + cw] = ex;          // half-exclusive, in place
            if (lane == 31) htot[pb][hh][cw] = inc;  // half total
        }
        __syncthreads();

        // ---- Pass 2: out = c + valid*(carry + excl); advance carry ----
        float4 ex = part[pb][q * 5 + l];
        float4 lo = htot[pb][0][l];
        float4 hi = htot[pb][1][l];
        float4 off;
        off.x = carry.x + ex.x; off.y = carry.y + ex.y;
        off.z = carry.z + ex.z; off.w = carry.w + ex.w;
        if (q >= 32) {                            // warp-uniform: add lower-half total
            off.x += lo.x; off.y += lo.y; off.z += lo.z; off.w += lo.w;
        }
        carry.x += lo.x + hi.x; carry.y += lo.y + hi.y;
        carry.z += lo.z + hi.z; carry.w += lo.w + hi.w;

        #pragma unroll
        for (int i = 0; i < RPT; i++) {
            float4 c = c_sm[pb][q * RPT + i][l];
            float4 o = c;
            if (r0 + i < len) {                   // warp-uniform
                o.x = c.x + off.x; o.y = c.y + off.y;
                o.z = c.z + off.z; o.w = c.w + off.w;
            }
            __stcs(op + colbase + (size_t)(r0 + i) * V4D, o);
        }
        // no trailing barrier: next tile uses the other smem buffer
    }

    // ============ Phase B: masked tail = pure streaming copy ============
    for (int it = nact; it < ITERS; it++) {
        const size_t base = colbase + (size_t)(it * TILE + q * RPT) * V4D;
        float4 v[RPT];
        #pragma unroll
        for (int i = 0; i < RPT; i++)
            v[i] = __ldcs(xp + base + (size_t)i * V4D);
        #pragma unroll
        for (int i = 0; i < RPT; i++)
            __stcs(op + base + (size_t)i * V4D, v[i]);
    }
}

extern "C" void kernel_launch(void* const* d_in, const int* in_sizes, int n_in,
                              void* d_out, int out_size) {
    const float* x   = (const float*)d_in[0];
    const void*  len = (const void*)d_in[1];
    float*       out = (float*)d_out;

    fused_kernel<<<NCTAS, THREADS>>>(x, len, out);
}

// round 9
// speedup vs baseline: 1.6214x; 1.2416x over previous
#include <cuda_runtime.h>
#include <cstdint>

// Problem shape (fixed by the dataset)
#define B  8
#define T  4096
#define D  1024
#define V4D 256                     // float4 per row
#define SLICES 64                   // 16-float D-slices
#define SLICE_V4 4                  // 4 float4 per slice
#define TILE 256                    // rows per tile iteration
#define QN   64                     // row-blocks per tile (TILE/RPT)
#define RPT  4                      // rows per thread per tile
#define THREADS 256                 // 64 q-blocks x 4 columns
#define ITERS (T / TILE)            // 16
#define NCTAS (B * SLICES)          // 512

// exact gelu via erff (polynomial path, no MUFU exp):
// jax.nn.gelu(approximate=False) = 0.5*x*(1+erf(x/sqrt(2)))
__device__ __forceinline__ float gelu_exact(float x) {
    return 0.5f * x * (1.0f + erff(x * 0.7071067811865476f));
}

// lengths dtype sniffing: reference asks for int64 but JAX default config
// (x64 disabled) emits int32. Reading the first 8 int32 words is safe under
// BOTH layouts. If genuine int64, every odd 32-bit word is the zero
// high-half (lengths < 4096). If int32, odd words are random lengths.
__device__ __forceinline__ int load_length(const void* lp, int b) {
    const int* p32 = (const int*)lp;
    bool is64 = (p32[1] == 0) & (p32[3] == 0) & (p32[5] == 0) & (p32[7] == 0);
    if (is64) return (int)((const long long*)lp)[b];
    return p32[b];
}

__global__ void __launch_bounds__(THREADS, 4)
fused_kernel(const float* __restrict__ x,
             const void* __restrict__ lengths,
             float* __restrict__ out) {
    // only scan state in smem now (c stays in registers), double-buffered
    __shared__ float4 part[2][QN * 5];            // stride 5: conflict-free
    __shared__ float4 htot[2][2][SLICE_V4];       // half-column totals

    const int tid  = threadIdx.x;
    const int q    = tid >> 2;      // row-block index  [0,64)
    const int l    = tid & 3;       // float4 column    [0,4)
    const int lane = tid & 31;
    const int w    = tid >> 5;      // warp id [0,8)
    const int cw   = w & 3;         // scan column of this warp
    const int hh   = w >> 2;        // scan half of this warp

    const int s = blockIdx.x & (SLICES - 1);
    const int b = blockIdx.x >> 6;
    const int len = load_length(lengths, b);
    const int nact = min(ITERS, (len + TILE - 1) / TILE);  // active tiles

    const size_t colbase = (size_t)b * T * V4D + (size_t)s * SLICE_V4 + l;
    const float4* xp = reinterpret_cast<const float4*>(x);
    float4*       op = reinterpret_cast<float4*>(out);

    float4 carry = make_float4(0.f, 0.f, 0.f, 0.f);

    // ================= Phase A: pipelined active tiles =================
    float4 cur[RPT];
    if (nact > 0) {
        const size_t base0 = colbase + (size_t)(q * RPT) * V4D;
        #pragma unroll
        for (int i = 0; i < RPT; i++)
            cur[i] = __ldcs(xp + base0 + (size_t)i * V4D);
    }

    for (int it = 0; it < nact; it++) {
        const int pb = it & 1;
        const int r0 = it * TILE + q * RPT;

        // ---- Pass 1: gelu once, serial prefix; c stays in registers ----
        float4 c[RPT];
        float4 run = make_float4(0.f, 0.f, 0.f, 0.f);
        #pragma unroll
        for (int i = 0; i < RPT; i++) {
            c[i] = cur[i];
            if (r0 + i < len) {                 // warp-uniform
                run.x += gelu_exact(cur[i].x);
                run.y += gelu_exact(cur[i].y);
                run.z += gelu_exact(cur[i].z);
                run.w += gelu_exact(cur[i].w);
                c[i].x += run.x; c[i].y += run.y;
                c[i].z += run.z; c[i].w += run.w;
            }
        }

        // ---- prefetch next tile NOW: loads fly across both barriers ----
        if (it + 1 < nact) {
            const size_t basen = colbase + (size_t)((it + 1) * TILE + q * RPT) * V4D;
            #pragma unroll
            for (int i = 0; i < RPT; i++)
                cur[i] = __ldcs(xp + basen + (size_t)i * V4D);
        }

        part[pb][q * 5 + l] = run;
        __syncthreads();

        // ---- two-level scan: warp w scans half hh of column cw ----
        {
            const int idx = hh * 32 + lane;
            float4 v = part[pb][idx * 5 + cw];
            float4 inc = v;
            #pragma unroll
            for (int d = 1; d < 32; d <<= 1) {
                float nx = __shfl_up_sync(0xffffffffu, inc.x, d);
                float ny = __shfl_up_sync(0xffffffffu, inc.y, d);
                float nz = __shfl_up_sync(0xffffffffu, inc.z, d);
                float nw = __shfl_up_sync(0xffffffffu, inc.w, d);
                if (lane >= d) { inc.x += nx; inc.y += ny; inc.z += nz; inc.w += nw; }
            }
            float4 ex;
            ex.x = inc.x - v.x; ex.y = inc.y - v.y;
            ex.z = inc.z - v.z; ex.w = inc.w - v.w;
            part[pb][idx * 5 + cw] = ex;          // half-exclusive, in place
            if (lane == 31) htot[pb][hh][cw] = inc;  // half total
        }
        __syncthreads();

        // ---- Pass 2: out = c + valid*(carry + excl); advance carry ----
        float4 ex = part[pb][q * 5 + l];
        float4 lo = htot[pb][0][l];
        float4 hi = htot[pb][1][l];
        float4 off;
        off.x = carry.x + ex.x; off.y = carry.y + ex.y;
        off.z = carry.z + ex.z; off.w = carry.w + ex.w;
        if (q >= 32) {                            // warp-uniform: add lower-half total
            off.x += lo.x; off.y += lo.y; off.z += lo.z; off.w += lo.w;
        }
        carry.x += lo.x + hi.x; carry.y += lo.y + hi.y;
        carry.z += lo.z + hi.z; carry.w += lo.w + hi.w;

        #pragma unroll
        for (int i = 0; i < RPT; i++) {
            float4 o = c[i];
            if (r0 + i < len) {                   // warp-uniform
                o.x += off.x; o.y += off.y;
                o.z += off.z; o.w += off.w;
            }
            __stcs(op + colbase + (size_t)(r0 + i) * V4D, o);
        }
        // no trailing barrier: next tile uses the other smem buffer
    }

    // ============ Phase B: masked tail = pure streaming copy ============
    for (int it = nact; it < ITERS; it++) {
        const size_t base = colbase + (size_t)(it * TILE + q * RPT) * V4D;
        float4 v[RPT];
        #pragma unroll
        for (int i = 0; i < RPT; i++)
            v[i] = __ldcs(xp + base + (size_t)i * V4D);
        #pragma unroll
        for (int i = 0; i < RPT; i++)
            __stcs(op + base + (size_t)i * V4D, v[i]);
    }
}

extern "C" void kernel_launch(void* const* d_in, const int* in_sizes, int n_in,
                              void* d_out, int out_size) {
    const float* x   = (const float*)d_in[0];
    const void*  len = (const void*)d_in[1];
    float*       out = (float*)d_out;

    fused_kernel<<<NCTAS, THREADS>>>(x, len, out);
}